// round 1
// baseline (speedup 1.0000x reference)
#include <cuda_runtime.h>
#include <cuda_bf16.h>

#define NN 50000
#define EE 800000
#define F1 128
#define F2 256   // HEADS*HID = 16*16
#define HEADS 16
#define HID 16
#define OUTC 64
#define NEG_SLOPE 0.2f
#define EPSV 1e-16f

// ---------------- scratch (static device arrays; no allocation) -------------
__device__ float g_h1[(size_t)NN * F2];      // layer-1 features  [N,256]
__device__ float g_out1[(size_t)NN * F2];    // layer-1 output    [N,256]
__device__ float g_h2[(size_t)NN * OUTC];    // layer-2 features  [N,64]
__device__ float g_as1[(size_t)NN * HEADS];
__device__ float g_ad1[(size_t)NN * HEADS];
__device__ float g_as2[NN];
__device__ float g_ad2[NN];
__device__ int   g_cnt[NN];
__device__ int   g_cur[NN];
__device__ int   g_off[NN + 1];
__device__ int   g_esrc[EE];
__device__ int   g_eflag;                    // 1 => edge_index is int32, 0 => int64

// ---------------- small helpers ---------------------------------------------
__device__ __forceinline__ float lrelu(float e) { return e > 0.f ? e : NEG_SLOPE * e; }

__device__ __forceinline__ void load_edge(const void* ei, int i, int flag, int& s, int& d) {
    if (flag) {
        const int* p = (const int*)ei;
        s = p[i]; d = p[EE + i];
    } else {
        const long long* p = (const long long*)ei;
        s = (int)p[i]; d = (int)p[EE + i];
    }
}

// ---------------- dtype detection -------------------------------------------
__global__ void detect_kernel(const void* ei) {
    __shared__ int nz;
    if (threadIdx.x == 0) nz = 0;
    __syncthreads();
    const int* w = (const int*)ei;
    for (int i = threadIdx.x; i < 512; i += blockDim.x)
        if (w[2 * i + 1] != 0) atomicOr(&nz, 1);
    __syncthreads();
    if (threadIdx.x == 0) g_eflag = nz ? 1 : 0;
}

// ---------------- CSR build --------------------------------------------------
__global__ void zero_kernel() {
    int i = blockIdx.x * blockDim.x + threadIdx.x;
    if (i < NN) { g_cnt[i] = 0; g_cur[i] = 0; }
}

__global__ void hist_kernel(const void* ei) {
    int i = blockIdx.x * blockDim.x + threadIdx.x;
    if (i >= EE) return;
    int flag = g_eflag, s, d;
    load_edge(ei, i, flag, s, d);
    atomicAdd(&g_cnt[d], 1);
}

__global__ void scan_kernel() {
    __shared__ int warpsum[32];
    int tid = threadIdx.x, lane = tid & 31, wid = tid >> 5;
    int run = 0;
    if (tid == 0) g_off[0] = 0;
    for (int base = 0; base < NN; base += 1024) {
        int i = base + tid;
        int x = (i < NN) ? g_cnt[i] : 0;
#pragma unroll
        for (int d = 1; d < 32; d <<= 1) {
            int t = __shfl_up_sync(0xffffffffu, x, d);
            if (lane >= d) x += t;
        }
        if (lane == 31) warpsum[wid] = x;
        __syncthreads();
        if (wid == 0) {
            int y = warpsum[lane];
#pragma unroll
            for (int d = 1; d < 32; d <<= 1) {
                int t = __shfl_up_sync(0xffffffffu, y, d);
                if (lane >= d) y += t;
            }
            warpsum[lane] = y;
        }
        __syncthreads();
        int add = (wid > 0) ? warpsum[wid - 1] : 0;
        if (i < NN) g_off[i + 1] = run + x + add;
        int total = warpsum[31];
        __syncthreads();
        run += total;
    }
}

__global__ void scatter_kernel(const void* ei) {
    int i = blockIdx.x * blockDim.x + threadIdx.x;
    if (i >= EE) return;
    int flag = g_eflag, s, d;
    load_edge(ei, i, flag, s, d);
    int pos = g_off[d] + atomicAdd(&g_cur[d], 1);
    g_esrc[pos] = s;
}

// ---------------- SGEMM (row-major, C[M,Kout] = A[M,KIN] * B[KIN,Kout]) -----
template <int KIN>
__global__ void sgemm64(const float* __restrict__ A, const float* __restrict__ B,
                        float* __restrict__ C, int M, int Kout) {
    __shared__ float As[32][68];
    __shared__ float Bs[32][68];
    int tid = threadIdx.x;                      // 256
    int row0 = blockIdx.y * 64, col0 = blockIdx.x * 64;
    int tx = tid & 15, ty = tid >> 4;
    float acc[4][4] = {};
    for (int k0 = 0; k0 < KIN; k0 += 32) {
#pragma unroll
        for (int l = 0; l < 2; l++) {
            int idx = tid + l * 256;            // 0..511
            int r = idx >> 3;                   // 0..63
            int c4 = idx & 7;
            float4 v = make_float4(0.f, 0.f, 0.f, 0.f);
            int gr = row0 + r;
            if (gr < M) v = *(const float4*)&A[(size_t)gr * KIN + k0 + c4 * 4];
            As[c4 * 4 + 0][r] = v.x; As[c4 * 4 + 1][r] = v.y;
            As[c4 * 4 + 2][r] = v.z; As[c4 * 4 + 3][r] = v.w;
        }
#pragma unroll
        for (int l = 0; l < 2; l++) {
            int idx = tid + l * 256;
            int r = idx >> 4;                   // 0..31
            int c4 = idx & 15;
            float4 v = *(const float4*)&B[(size_t)(k0 + r) * Kout + col0 + c4 * 4];
            *(float4*)&Bs[r][c4 * 4] = v;
        }
        __syncthreads();
#pragma unroll
        for (int k = 0; k < 32; k++) {
            float a[4], b[4];
#pragma unroll
            for (int i = 0; i < 4; i++) a[i] = As[k][ty * 4 + i];
#pragma unroll
            for (int j = 0; j < 4; j++) b[j] = Bs[k][tx * 4 + j];
#pragma unroll
            for (int i = 0; i < 4; i++)
#pragma unroll
                for (int j = 0; j < 4; j++) acc[i][j] += a[i] * b[j];
        }
        __syncthreads();
    }
#pragma unroll
    for (int i = 0; i < 4; i++) {
        int gr = row0 + ty * 4 + i;
        if (gr < M) {
            float4 v = make_float4(acc[i][0], acc[i][1], acc[i][2], acc[i][3]);
            *(float4*)&C[(size_t)gr * Kout + col0 + tx * 4] = v;
        }
    }
}

// ---------------- per-node attention coefficients ----------------------------
__global__ void alpha1_kernel(const float* __restrict__ av_s, const float* __restrict__ av_d) {
    int i = blockIdx.x * blockDim.x + threadIdx.x;     // over N*HEADS
    if (i >= NN * HEADS) return;
    int n = i >> 4, h = i & 15;
    const float* hp = g_h1 + (size_t)n * F2 + h * HID;
    float sa = 0.f, sd = 0.f;
#pragma unroll
    for (int c = 0; c < HID; c++) {
        float v = hp[c];
        sa += v * av_s[h * HID + c];
        sd += v * av_d[h * HID + c];
    }
    g_as1[i] = sa; g_ad1[i] = sd;
}

__global__ void alpha2_kernel(const float* __restrict__ av_s, const float* __restrict__ av_d) {
    int n = blockIdx.x * blockDim.x + threadIdx.x;
    if (n >= NN) return;
    const float* hp = g_h2 + (size_t)n * OUTC;
    float sa = 0.f, sd = 0.f;
#pragma unroll
    for (int c = 0; c < OUTC; c++) {
        float v = hp[c];
        sa += v * av_s[c];
        sd += v * av_d[c];
    }
    g_as2[n] = sa; g_ad2[n] = sd;
}

// ---------------- layer-1 softmax aggregation (warp per dst) ----------------
__global__ void agg1_kernel(const float* __restrict__ b1) {
    int w = (blockIdx.x * blockDim.x + threadIdx.x) >> 5;
    int lane = threadIdx.x & 31;
    if (w >= NN) return;
    int dst = w;
    int beg = g_off[dst], end = g_off[dst + 1];
    int h = lane & 15;
    float adh = g_ad1[(size_t)dst * HEADS + h];
    float es = lrelu(g_as1[(size_t)dst * HEADS + h] + adh);   // self-loop logit
    float m = es;
    int sub = lane >> 4;
    for (int i = beg + sub; i < end; i += 2) {
        int s = g_esrc[i];
        m = fmaxf(m, lrelu(g_as1[(size_t)s * HEADS + h] + adh));
    }
    m = fmaxf(m, __shfl_xor_sync(0xffffffffu, m, 16));

    float exs = __expf(es - m);
    float denom = exs;
    int srcl = lane >> 1;                                       // head owning my channels
    float ex_hc = __shfl_sync(0xffffffffu, exs, srcl);
    const float4* hp = (const float4*)(g_h1 + (size_t)dst * F2 + lane * 8);
    float4 v0 = hp[0], v1 = hp[1];
    float4 a0 = make_float4(v0.x * ex_hc, v0.y * ex_hc, v0.z * ex_hc, v0.w * ex_hc);
    float4 a1 = make_float4(v1.x * ex_hc, v1.y * ex_hc, v1.z * ex_hc, v1.w * ex_hc);

    for (int i = beg; i < end; i++) {
        int s = g_esrc[i];
        float e = lrelu(g_as1[(size_t)s * HEADS + h] + adh);
        float ex = __expf(e - m);
        denom += ex;
        float exm = __shfl_sync(0xffffffffu, ex, srcl);
        const float4* sp = (const float4*)(g_h1 + (size_t)s * F2 + lane * 8);
        float4 s0 = sp[0], s1 = sp[1];
        a0.x += s0.x * exm; a0.y += s0.y * exm; a0.z += s0.z * exm; a0.w += s0.w * exm;
        a1.x += s1.x * exm; a1.y += s1.y * exm; a1.z += s1.z * exm; a1.w += s1.w * exm;
    }
    float den = __shfl_sync(0xffffffffu, denom, srcl) + EPSV;
    float inv = 1.0f / den;
    int ch0 = lane * 8;
    float4 o0 = make_float4(a0.x * inv + b1[ch0 + 0], a0.y * inv + b1[ch0 + 1],
                            a0.z * inv + b1[ch0 + 2], a0.w * inv + b1[ch0 + 3]);
    float4 o1 = make_float4(a1.x * inv + b1[ch0 + 4], a1.y * inv + b1[ch0 + 5],
                            a1.z * inv + b1[ch0 + 6], a1.w * inv + b1[ch0 + 7]);
    float4* op = (float4*)(g_out1 + (size_t)dst * F2 + ch0);
    op[0] = o0; op[1] = o1;
}

// ---------------- layer-2 softmax aggregation + sigmoid ---------------------
__global__ void agg2_kernel(const float* __restrict__ b2, float* __restrict__ out) {
    int w = (blockIdx.x * blockDim.x + threadIdx.x) >> 5;
    int lane = threadIdx.x & 31;
    if (w >= NN) return;
    int dst = w;
    int beg = g_off[dst], end = g_off[dst + 1];
    float adw = g_ad2[dst];
    float es = lrelu(g_as2[dst] + adw);
    float m = es;
    for (int i = beg + lane; i < end; i += 32)
        m = fmaxf(m, lrelu(g_as2[g_esrc[i]] + adw));
#pragma unroll
    for (int d = 16; d >= 1; d >>= 1)
        m = fmaxf(m, __shfl_xor_sync(0xffffffffu, m, d));

    float exs = __expf(es - m);
    float denom = exs;
    float2 v = *(const float2*)(g_h2 + (size_t)dst * OUTC + lane * 2);
    float2 acc = make_float2(v.x * exs, v.y * exs);
    for (int i = beg; i < end; i++) {
        int s = g_esrc[i];
        float ex = __expf(lrelu(g_as2[s] + adw) - m);
        denom += ex;
        float2 sv = *(const float2*)(g_h2 + (size_t)s * OUTC + lane * 2);
        acc.x += sv.x * ex; acc.y += sv.y * ex;
    }
    float inv = 1.0f / (denom + EPSV);
    float x0 = acc.x * inv + b2[lane * 2 + 0];
    float x1 = acc.y * inv + b2[lane * 2 + 1];
    float2 o = make_float2(1.0f / (1.0f + __expf(-x0)), 1.0f / (1.0f + __expf(-x1)));
    *(float2*)(out + (size_t)dst * OUTC + lane * 2) = o;
}

// ---------------- launcher ----------------------------------------------------
extern "C" void kernel_launch(void* const* d_in, const int* in_sizes, int n_in,
                              void* d_out, int out_size) {
    const float* x      = (const float*)d_in[0];
    const void*  ei     = d_in[1];
    const float* W1     = (const float*)d_in[2];
    const float* a_src1 = (const float*)d_in[3];
    const float* a_dst1 = (const float*)d_in[4];
    const float* b1     = (const float*)d_in[5];
    const float* W2     = (const float*)d_in[6];
    const float* a_src2 = (const float*)d_in[7];
    const float* a_dst2 = (const float*)d_in[8];
    const float* b2     = (const float*)d_in[9];
    float* out = (float*)d_out;

    // CSR build
    detect_kernel<<<1, 256>>>(ei);
    zero_kernel<<<(NN + 255) / 256, 256>>>();
    hist_kernel<<<(EE + 255) / 256, 256>>>(ei);
    scan_kernel<<<1, 1024>>>();
    scatter_kernel<<<(EE + 255) / 256, 256>>>(ei);

    // layer 1
    {
        float* h1;
        cudaGetSymbolAddress((void**)&h1, g_h1);
        dim3 grid(F2 / 64, (NN + 63) / 64);
        sgemm64<F1><<<grid, 256>>>(x, W1, h1, NN, F2);
    }
    alpha1_kernel<<<(NN * HEADS + 255) / 256, 256>>>(a_src1, a_dst1);
    agg1_kernel<<<(NN * 32 + 255) / 256, 256>>>(b1);

    // layer 2
    {
        float *o1, *h2;
        cudaGetSymbolAddress((void**)&o1, g_out1);
        cudaGetSymbolAddress((void**)&h2, g_h2);
        dim3 grid(OUTC / 64, (NN + 63) / 64);
        sgemm64<F2><<<grid, 256>>>(o1, W2, h2, NN, OUTC);
    }
    alpha2_kernel<<<(NN + 255) / 256, 256>>>(a_src2, a_dst2);
    agg2_kernel<<<(NN * 32 + 255) / 256, 256>>>(b2, out);
}

// round 2
// speedup vs baseline: 1.3026x; 1.3026x over previous
#include <cuda_runtime.h>
#include <cuda_bf16.h>

#define NN 50000
#define EE 800000
#define F1 128
#define F2 256   // HEADS*HID
#define HEADS 16
#define HID 16
#define OUTC 64
#define NEG_SLOPE 0.2f
#define EPSV 1e-16f
#define SCAN_BLK 49   // ceil(50000/1024)

// ---------------- scratch ----------------------------------------------------
__device__ float g_h1[(size_t)NN * F2];
__device__ float g_out1[(size_t)NN * F2];
__device__ float g_h2[(size_t)NN * OUTC];
__device__ float g_as1[(size_t)NN * HEADS];
__device__ float g_ad1[(size_t)NN * HEADS];
__device__ float g_as2[NN];
__device__ float g_ad2[NN];
__device__ int   g_cnt[NN];
__device__ int   g_cur[NN];
__device__ int   g_off[NN + 1];
__device__ int   g_esrc[EE];
__device__ int   g_bsum[64];
__device__ int   g_bpre[64];
__device__ int   g_eflag;

// ---------------- helpers -----------------------------------------------------
__device__ __forceinline__ float lrelu(float e) { return e > 0.f ? e : NEG_SLOPE * e; }

__device__ __forceinline__ unsigned long long pack2(float x, float y) {
    unsigned long long r;
    asm("mov.b64 %0, {%1, %2};" : "=l"(r) : "f"(x), "f"(y));
    return r;
}
__device__ __forceinline__ float2 unpack2(unsigned long long v) {
    float2 f;
    asm("mov.b64 {%0, %1}, %2;" : "=f"(f.x), "=f"(f.y) : "l"(v));
    return f;
}
__device__ __forceinline__ void fma2(unsigned long long& d, unsigned long long a,
                                     unsigned long long b) {
    asm("fma.rn.f32x2 %0, %1, %2, %3;" : "=l"(d) : "l"(a), "l"(b), "l"(d));
}

__device__ __forceinline__ void load_edge(const void* ei, int i, int flag, int& s, int& d) {
    if (flag) {
        const int* p = (const int*)ei;
        s = p[i]; d = p[EE + i];
    } else {
        const long long* p = (const long long*)ei;
        s = (int)p[i]; d = (int)p[EE + i];
    }
}

// ---------------- dtype detect -------------------------------------------------
__global__ void detect_kernel(const void* ei) {
    __shared__ int nz;
    if (threadIdx.x == 0) nz = 0;
    __syncthreads();
    const int* w = (const int*)ei;
    for (int i = threadIdx.x; i < 512; i += blockDim.x)
        if (w[2 * i + 1] != 0) atomicOr(&nz, 1);
    __syncthreads();
    if (threadIdx.x == 0) g_eflag = nz ? 1 : 0;
}

// ---------------- CSR build -----------------------------------------------------
__global__ void zero_kernel() {
    int i = blockIdx.x * blockDim.x + threadIdx.x;
    if (i < NN) { g_cnt[i] = 0; g_cur[i] = 0; }
}

__global__ void hist_kernel(const void* ei) {
    int i = blockIdx.x * blockDim.x + threadIdx.x;
    if (i >= EE) return;
    int s, d;
    load_edge(ei, i, g_eflag, s, d);
    atomicAdd(&g_cnt[d], 1);
}

__global__ void scanA_kernel() {
    __shared__ int wsum[32];
    int i = blockIdx.x * 1024 + threadIdx.x;
    int lane = threadIdx.x & 31, wid = threadIdx.x >> 5;
    int x = (i < NN) ? g_cnt[i] : 0;
    int incl = x;
#pragma unroll
    for (int d = 1; d < 32; d <<= 1) {
        int t = __shfl_up_sync(0xffffffffu, incl, d);
        if (lane >= d) incl += t;
    }
    if (lane == 31) wsum[wid] = incl;
    __syncthreads();
    if (wid == 0) {
        int y = wsum[lane];
#pragma unroll
        for (int d = 1; d < 32; d <<= 1) {
            int t = __shfl_up_sync(0xffffffffu, y, d);
            if (lane >= d) y += t;
        }
        wsum[lane] = y;
    }
    __syncthreads();
    if (wid > 0) incl += wsum[wid - 1];
    if (i < NN) g_off[i + 1] = incl;
    if (threadIdx.x == 1023) g_bsum[blockIdx.x] = incl;
}

__global__ void scanB_kernel() {
    __shared__ int s[64];
    int t = threadIdx.x;
    int v0 = (t < SCAN_BLK) ? g_bsum[t] : 0;
    s[t] = v0;
    __syncthreads();
#pragma unroll
    for (int d = 1; d < 64; d <<= 1) {
        int v = (t >= d) ? s[t - d] : 0;
        __syncthreads();
        s[t] += v;
        __syncthreads();
    }
    g_bpre[t] = s[t] - v0;   // exclusive prefix of block sums
}

__global__ void scanC_kernel() {
    int i = blockIdx.x * 1024 + threadIdx.x;
    if (i < NN) g_off[i + 1] += g_bpre[blockIdx.x];
    if (i == 0) g_off[0] = 0;
}

__global__ void scatter_kernel(const void* ei) {
    int i = blockIdx.x * blockDim.x + threadIdx.x;
    if (i >= EE) return;
    int s, d;
    load_edge(ei, i, g_eflag, s, d);
    int pos = g_off[d] + atomicAdd(&g_cur[d], 1);
    g_esrc[pos] = s;
}

// ---------------- fused GEMM (f32x2) + alpha dot products -----------------------
// C[M,KOUT] = A[M,KIN] @ B[KIN,KOUT]; tile 128x64, thread 8 rows x 4 cols.
// L1HEADS: epilogue computes per-(row,head of 16ch) dots with avs/avd (16 heads).
// Otherwise single 64-ch head dot per row.
template <int KIN, int KOUT, bool L1HEADS>
__global__ void gemm_fused(const float* __restrict__ A, const float* __restrict__ B,
                           float* __restrict__ C,
                           const float* __restrict__ avs, const float* __restrict__ avd,
                           float* __restrict__ as_out, float* __restrict__ ad_out,
                           int M) {
    __shared__ float As[32][132];   // transposed: As[k][row]
    __shared__ float Bs[32][68];
    int tid = threadIdx.x;           // 256
    int tx = tid & 15, ty = tid >> 4;
    int row0 = blockIdx.y * 128, col0 = blockIdx.x * 64;

    unsigned long long acc[8][2];
#pragma unroll
    for (int i = 0; i < 8; i++) { acc[i][0] = 0ull; acc[i][1] = 0ull; }

    for (int k0 = 0; k0 < KIN; k0 += 32) {
#pragma unroll
        for (int l = 0; l < 4; l++) {
            int idx = tid + l * 256;          // 0..1023 over 128 rows x 8 f4-cols
            int r = idx >> 3, c4 = idx & 7;
            float4 v = make_float4(0.f, 0.f, 0.f, 0.f);
            int gr = row0 + r;
            if (gr < M) v = *(const float4*)&A[(size_t)gr * KIN + k0 + c4 * 4];
            As[c4 * 4 + 0][r] = v.x; As[c4 * 4 + 1][r] = v.y;
            As[c4 * 4 + 2][r] = v.z; As[c4 * 4 + 3][r] = v.w;
        }
#pragma unroll
        for (int l = 0; l < 2; l++) {
            int idx = tid + l * 256;          // 0..511 over 32 rows x 16 f4-cols
            int r = idx >> 4, c4 = idx & 15;
            float4 v = *(const float4*)&B[(size_t)(k0 + r) * KOUT + col0 + c4 * 4];
            *(float4*)&Bs[r][c4 * 4] = v;
        }
        __syncthreads();
#pragma unroll
        for (int k = 0; k < 32; k++) {
            float4 aA = *(const float4*)&As[k][ty * 8];
            float4 aB = *(const float4*)&As[k][ty * 8 + 4];
            float4 bq = *(const float4*)&Bs[k][tx * 4];
            unsigned long long b0 = pack2(bq.x, bq.y);
            unsigned long long b1 = pack2(bq.z, bq.w);
            unsigned long long a2[8];
            a2[0] = pack2(aA.x, aA.x); a2[1] = pack2(aA.y, aA.y);
            a2[2] = pack2(aA.z, aA.z); a2[3] = pack2(aA.w, aA.w);
            a2[4] = pack2(aB.x, aB.x); a2[5] = pack2(aB.y, aB.y);
            a2[6] = pack2(aB.z, aB.z); a2[7] = pack2(aB.w, aB.w);
#pragma unroll
            for (int i = 0; i < 8; i++) {
                fma2(acc[i][0], a2[i], b0);
                fma2(acc[i][1], a2[i], b1);
            }
        }
        __syncthreads();
    }

    // unpack + store + fused alpha dots
    float f[8][4];
#pragma unroll
    for (int i = 0; i < 8; i++) {
        float2 p0 = unpack2(acc[i][0]), p1 = unpack2(acc[i][1]);
        f[i][0] = p0.x; f[i][1] = p0.y; f[i][2] = p1.x; f[i][3] = p1.y;
    }
#pragma unroll
    for (int i = 0; i < 8; i++) {
        int gr = row0 + ty * 8 + i;
        if (gr < M) {
            float4 v = make_float4(f[i][0], f[i][1], f[i][2], f[i][3]);
            *(float4*)&C[(size_t)gr * KOUT + col0 + tx * 4] = v;
        }
    }

    if (L1HEADS) {
        // head spans 16 channels = 4 threads with consecutive tx (adjacent lanes)
        int h = blockIdx.x * 4 + (tx >> 2);
        int cbase = (tx & 3) * 4;
        float wva[4], wvd[4];
#pragma unroll
        for (int j = 0; j < 4; j++) {
            wva[j] = avs[h * HID + cbase + j];
            wvd[j] = avd[h * HID + cbase + j];
        }
#pragma unroll
        for (int i = 0; i < 8; i++) {
            float ps = 0.f, pd = 0.f;
#pragma unroll
            for (int j = 0; j < 4; j++) { ps += f[i][j] * wva[j]; pd += f[i][j] * wvd[j]; }
            ps += __shfl_xor_sync(0xffffffffu, ps, 1);
            pd += __shfl_xor_sync(0xffffffffu, pd, 1);
            ps += __shfl_xor_sync(0xffffffffu, ps, 2);
            pd += __shfl_xor_sync(0xffffffffu, pd, 2);
            int gr = row0 + ty * 8 + i;
            if ((tx & 3) == 0 && gr < M) {
                as_out[(size_t)gr * HEADS + h] = ps;
                ad_out[(size_t)gr * HEADS + h] = pd;
            }
        }
    } else {
        // single head over all 64 channels (16 threads per row)
        float wva[4], wvd[4];
#pragma unroll
        for (int j = 0; j < 4; j++) {
            wva[j] = avs[tx * 4 + j];
            wvd[j] = avd[tx * 4 + j];
        }
#pragma unroll
        for (int i = 0; i < 8; i++) {
            float ps = 0.f, pd = 0.f;
#pragma unroll
            for (int j = 0; j < 4; j++) { ps += f[i][j] * wva[j]; pd += f[i][j] * wvd[j]; }
#pragma unroll
            for (int d = 1; d <= 8; d <<= 1) {
                ps += __shfl_xor_sync(0xffffffffu, ps, d);
                pd += __shfl_xor_sync(0xffffffffu, pd, d);
            }
            int gr = row0 + ty * 8 + i;
            if (tx == 0 && gr < M) {
                as_out[gr] = ps;
                ad_out[gr] = pd;
            }
        }
    }
}

// ---------------- layer-1 aggregation (warp/dst, single pass, no max) ----------
__global__ void agg1_kernel(const float* __restrict__ b1) {
    int w = (blockIdx.x * blockDim.x + threadIdx.x) >> 5;
    int lane = threadIdx.x & 31;
    if (w >= NN) return;
    int dst = w;
    int beg = g_off[dst], end = g_off[dst + 1];
    int h = lane & 15;
    float adh = g_ad1[(size_t)dst * HEADS + h];
    float exs = __expf(lrelu(g_as1[(size_t)dst * HEADS + h] + adh));
    float denom = exs;
    int srcl = lane >> 1;
    float exm = __shfl_sync(0xffffffffu, exs, srcl);
    const float4* hp = (const float4*)(g_h1 + (size_t)dst * F2 + lane * 8);
    float4 v0 = hp[0], v1 = hp[1];
    float4 a0 = make_float4(v0.x * exm, v0.y * exm, v0.z * exm, v0.w * exm);
    float4 a1 = make_float4(v1.x * exm, v1.y * exm, v1.z * exm, v1.w * exm);

    for (int i = beg; i < end; i++) {
        int s = g_esrc[i];
        float ex = __expf(lrelu(g_as1[(size_t)s * HEADS + h] + adh));
        denom += ex;
        float em = __shfl_sync(0xffffffffu, ex, srcl);
        const float4* sp = (const float4*)(g_h1 + (size_t)s * F2 + lane * 8);
        float4 s0 = sp[0], s1 = sp[1];
        a0.x += s0.x * em; a0.y += s0.y * em; a0.z += s0.z * em; a0.w += s0.w * em;
        a1.x += s1.x * em; a1.y += s1.y * em; a1.z += s1.z * em; a1.w += s1.w * em;
    }
    float den = __shfl_sync(0xffffffffu, denom, srcl) + EPSV;
    float inv = 1.0f / den;
    int ch0 = lane * 8;
    float4 o0 = make_float4(a0.x * inv + b1[ch0 + 0], a0.y * inv + b1[ch0 + 1],
                            a0.z * inv + b1[ch0 + 2], a0.w * inv + b1[ch0 + 3]);
    float4 o1 = make_float4(a1.x * inv + b1[ch0 + 4], a1.y * inv + b1[ch0 + 5],
                            a1.z * inv + b1[ch0 + 6], a1.w * inv + b1[ch0 + 7]);
    float4* op = (float4*)(g_out1 + (size_t)dst * F2 + ch0);
    op[0] = o0; op[1] = o1;
}

// ---------------- layer-2 aggregation + sigmoid (single pass, no max) ----------
__global__ void agg2_kernel(const float* __restrict__ b2, float* __restrict__ out) {
    int w = (blockIdx.x * blockDim.x + threadIdx.x) >> 5;
    int lane = threadIdx.x & 31;
    if (w >= NN) return;
    int dst = w;
    int beg = g_off[dst], end = g_off[dst + 1];
    float adw = g_ad2[dst];
    float exs = __expf(lrelu(g_as2[dst] + adw));
    float denom = exs;
    float2 v = *(const float2*)(g_h2 + (size_t)dst * OUTC + lane * 2);
    float2 acc = make_float2(v.x * exs, v.y * exs);
    for (int i = beg; i < end; i++) {
        int s = g_esrc[i];
        float ex = __expf(lrelu(g_as2[s] + adw));
        denom += ex;
        float2 sv = *(const float2*)(g_h2 + (size_t)s * OUTC + lane * 2);
        acc.x += sv.x * ex; acc.y += sv.y * ex;
    }
    float inv = 1.0f / (denom + EPSV);
    float x0 = acc.x * inv + b2[lane * 2 + 0];
    float x1 = acc.y * inv + b2[lane * 2 + 1];
    float2 o = make_float2(1.0f / (1.0f + __expf(-x0)), 1.0f / (1.0f + __expf(-x1)));
    *(float2*)(out + (size_t)dst * OUTC + lane * 2) = o;
}

// ---------------- launcher -------------------------------------------------------
extern "C" void kernel_launch(void* const* d_in, const int* in_sizes, int n_in,
                              void* d_out, int out_size) {
    const float* x      = (const float*)d_in[0];
    const void*  ei     = d_in[1];
    const float* W1     = (const float*)d_in[2];
    const float* a_src1 = (const float*)d_in[3];
    const float* a_dst1 = (const float*)d_in[4];
    const float* b1     = (const float*)d_in[5];
    const float* W2     = (const float*)d_in[6];
    const float* a_src2 = (const float*)d_in[7];
    const float* a_dst2 = (const float*)d_in[8];
    const float* b2     = (const float*)d_in[9];
    float* out = (float*)d_out;

    float *h1, *o1, *h2, *as1, *ad1, *as2, *ad2;
    cudaGetSymbolAddress((void**)&h1, g_h1);
    cudaGetSymbolAddress((void**)&o1, g_out1);
    cudaGetSymbolAddress((void**)&h2, g_h2);
    cudaGetSymbolAddress((void**)&as1, g_as1);
    cudaGetSymbolAddress((void**)&ad1, g_ad1);
    cudaGetSymbolAddress((void**)&as2, g_as2);
    cudaGetSymbolAddress((void**)&ad2, g_ad2);

    // CSR build
    detect_kernel<<<1, 256>>>(ei);
    zero_kernel<<<(NN + 255) / 256, 256>>>();
    hist_kernel<<<(EE + 255) / 256, 256>>>(ei);
    scanA_kernel<<<SCAN_BLK, 1024>>>();
    scanB_kernel<<<1, 64>>>();
    scanC_kernel<<<SCAN_BLK, 1024>>>();
    scatter_kernel<<<(EE + 255) / 256, 256>>>(ei);

    // layer 1: GEMM + fused alpha, then aggregate
    {
        dim3 grid(F2 / 64, (NN + 127) / 128);
        gemm_fused<F1, F2, true><<<grid, 256>>>(x, W1, h1, a_src1, a_dst1, as1, ad1, NN);
    }
    agg1_kernel<<<(NN * 32 + 255) / 256, 256>>>(b1);

    // layer 2
    {
        dim3 grid(OUTC / 64, (NN + 127) / 128);
        gemm_fused<F2, OUTC, false><<<grid, 256>>>(o1, W2, h2, a_src2, a_dst2, as2, ad2, NN);
    }
    agg2_kernel<<<(NN * 32 + 255) / 256, 256>>>(b2, out);
}

// round 3
// speedup vs baseline: 1.5933x; 1.2231x over previous
#include <cuda_runtime.h>
#include <cuda_fp16.h>
#include <cuda_bf16.h>

#define NN 50000
#define EE 800000
#define F1 128
#define F2 256   // HEADS*HID
#define HEADS 16
#define HID 16
#define OUTC 64
#define NEG_SLOPE 0.2f
#define EPSV 1e-16f
#define SCAN_BLK 49   // ceil(50000/1024)

// ---------------- scratch ----------------------------------------------------
__device__ __half g_h1h[(size_t)NN * F2];    // layer-1 features (half) [N,256]
__device__ float  g_out1[(size_t)NN * F2];   // layer-1 output (fp32)   [N,256]
__device__ __half g_h2h[(size_t)NN * OUTC];  // layer-2 features (half) [N,64]
__device__ float  g_as1[(size_t)NN * HEADS];
__device__ float  g_ad1[(size_t)NN * HEADS];
__device__ float  g_as2[NN];
__device__ float  g_ad2[NN];
__device__ int    g_cnt[NN];
__device__ int    g_cur[NN];
__device__ int    g_off[NN + 1];
__device__ int    g_esrc[EE];
__device__ int    g_bsum[64];
__device__ int    g_bpre[64];
__device__ int    g_eflag;

// ---------------- helpers -----------------------------------------------------
__device__ __forceinline__ float lrelu(float e) { return e > 0.f ? e : NEG_SLOPE * e; }

__device__ __forceinline__ unsigned long long pack2(float x, float y) {
    unsigned long long r;
    asm("mov.b64 %0, {%1, %2};" : "=l"(r) : "f"(x), "f"(y));
    return r;
}
__device__ __forceinline__ float2 unpack2(unsigned long long v) {
    float2 f;
    asm("mov.b64 {%0, %1}, %2;" : "=f"(f.x), "=f"(f.y) : "l"(v));
    return f;
}
__device__ __forceinline__ void fma2(unsigned long long& d, unsigned long long a,
                                     unsigned long long b) {
    asm("fma.rn.f32x2 %0, %1, %2, %3;" : "=l"(d) : "l"(a), "l"(b), "l"(d));
}

__device__ __forceinline__ void load_edge(const void* ei, int i, int flag, int& s, int& d) {
    if (flag) {
        const int* p = (const int*)ei;
        s = p[i]; d = p[EE + i];
    } else {
        const long long* p = (const long long*)ei;
        s = (int)p[i]; d = (int)p[EE + i];
    }
}

// ---------------- init: zero counters + dtype detect ---------------------------
__global__ void init_kernel(const void* ei) {
    int i = blockIdx.x * blockDim.x + threadIdx.x;
    if (i < NN) { g_cnt[i] = 0; g_cur[i] = 0; }
    if (blockIdx.x == 0) {
        __shared__ int nz;
        if (threadIdx.x == 0) nz = 0;
        __syncthreads();
        const int* w = (const int*)ei;
        int any = 0;
        for (int j = threadIdx.x; j < 512; j += blockDim.x)
            if (w[2 * j + 1] != 0) any = 1;
        if (any) atomicOr(&nz, 1);
        __syncthreads();
        if (threadIdx.x == 0) g_eflag = nz ? 1 : 0;
    }
}

// ---------------- CSR build -----------------------------------------------------
__global__ void hist_kernel(const void* ei) {
    int i = blockIdx.x * blockDim.x + threadIdx.x;
    if (i >= EE) return;
    int s, d;
    load_edge(ei, i, g_eflag, s, d);
    atomicAdd(&g_cnt[d], 1);
}

__global__ void scanA_kernel() {
    __shared__ int wsum[32];
    int i = blockIdx.x * 1024 + threadIdx.x;
    int lane = threadIdx.x & 31, wid = threadIdx.x >> 5;
    int x = (i < NN) ? g_cnt[i] : 0;
    int incl = x;
#pragma unroll
    for (int d = 1; d < 32; d <<= 1) {
        int t = __shfl_up_sync(0xffffffffu, incl, d);
        if (lane >= d) incl += t;
    }
    if (lane == 31) wsum[wid] = incl;
    __syncthreads();
    if (wid == 0) {
        int y = wsum[lane];
#pragma unroll
        for (int d = 1; d < 32; d <<= 1) {
            int t = __shfl_up_sync(0xffffffffu, y, d);
            if (lane >= d) y += t;
        }
        wsum[lane] = y;
    }
    __syncthreads();
    if (wid > 0) incl += wsum[wid - 1];
    if (i < NN) g_off[i + 1] = incl;
    if (threadIdx.x == 1023) g_bsum[blockIdx.x] = incl;
}

__global__ void scanB_kernel() {
    __shared__ int s[64];
    int t = threadIdx.x;
    int v0 = (t < SCAN_BLK) ? g_bsum[t] : 0;
    s[t] = v0;
    __syncthreads();
#pragma unroll
    for (int d = 1; d < 64; d <<= 1) {
        int v = (t >= d) ? s[t - d] : 0;
        __syncthreads();
        s[t] += v;
        __syncthreads();
    }
    g_bpre[t] = s[t] - v0;
}

__global__ void scanC_kernel() {
    int i = blockIdx.x * 1024 + threadIdx.x;
    if (i < NN) g_off[i + 1] += g_bpre[blockIdx.x];
    if (i == 0) g_off[0] = 0;
}

__global__ void scatter_kernel(const void* ei) {
    int i = blockIdx.x * blockDim.x + threadIdx.x;
    if (i >= EE) return;
    int s, d;
    load_edge(ei, i, g_eflag, s, d);
    int pos = g_off[d] + atomicAdd(&g_cur[d], 1);
    g_esrc[pos] = s;
}

// ---------------- fused GEMM (f32x2) + alpha dots, optional half output --------
template <int KIN, int KOUT, bool L1HEADS, bool CHALF>
__global__ void gemm_fused(const float* __restrict__ A, const float* __restrict__ B,
                           void* __restrict__ Cv,
                           const float* __restrict__ avs, const float* __restrict__ avd,
                           float* __restrict__ as_out, float* __restrict__ ad_out,
                           int M) {
    __shared__ float As[32][132];   // transposed: As[k][row]
    __shared__ float Bs[32][68];
    int tid = threadIdx.x;           // 256
    int tx = tid & 15, ty = tid >> 4;
    int row0 = blockIdx.y * 128, col0 = blockIdx.x * 64;

    unsigned long long acc[8][2];
#pragma unroll
    for (int i = 0; i < 8; i++) { acc[i][0] = 0ull; acc[i][1] = 0ull; }

    for (int k0 = 0; k0 < KIN; k0 += 32) {
#pragma unroll
        for (int l = 0; l < 4; l++) {
            int idx = tid + l * 256;
            int r = idx >> 3, c4 = idx & 7;
            float4 v = make_float4(0.f, 0.f, 0.f, 0.f);
            int gr = row0 + r;
            if (gr < M) v = *(const float4*)&A[(size_t)gr * KIN + k0 + c4 * 4];
            As[c4 * 4 + 0][r] = v.x; As[c4 * 4 + 1][r] = v.y;
            As[c4 * 4 + 2][r] = v.z; As[c4 * 4 + 3][r] = v.w;
        }
#pragma unroll
        for (int l = 0; l < 2; l++) {
            int idx = tid + l * 256;
            int r = idx >> 4, c4 = idx & 15;
            float4 v = *(const float4*)&B[(size_t)(k0 + r) * KOUT + col0 + c4 * 4];
            *(float4*)&Bs[r][c4 * 4] = v;
        }
        __syncthreads();
#pragma unroll
        for (int k = 0; k < 32; k++) {
            float4 aA = *(const float4*)&As[k][ty * 8];
            float4 aB = *(const float4*)&As[k][ty * 8 + 4];
            float4 bq = *(const float4*)&Bs[k][tx * 4];
            unsigned long long b0 = pack2(bq.x, bq.y);
            unsigned long long b1 = pack2(bq.z, bq.w);
            unsigned long long a2[8];
            a2[0] = pack2(aA.x, aA.x); a2[1] = pack2(aA.y, aA.y);
            a2[2] = pack2(aA.z, aA.z); a2[3] = pack2(aA.w, aA.w);
            a2[4] = pack2(aB.x, aB.x); a2[5] = pack2(aB.y, aB.y);
            a2[6] = pack2(aB.z, aB.z); a2[7] = pack2(aB.w, aB.w);
#pragma unroll
            for (int i = 0; i < 8; i++) {
                fma2(acc[i][0], a2[i], b0);
                fma2(acc[i][1], a2[i], b1);
            }
        }
        __syncthreads();
    }

    float f[8][4];
#pragma unroll
    for (int i = 0; i < 8; i++) {
        float2 p0 = unpack2(acc[i][0]), p1 = unpack2(acc[i][1]);
        f[i][0] = p0.x; f[i][1] = p0.y; f[i][2] = p1.x; f[i][3] = p1.y;
    }

#pragma unroll
    for (int i = 0; i < 8; i++) {
        int gr = row0 + ty * 8 + i;
        if (gr < M) {
            if (CHALF) {
                __half* Ch = (__half*)Cv;
                __half2 p0 = __floats2half2_rn(f[i][0], f[i][1]);
                __half2 p1 = __floats2half2_rn(f[i][2], f[i][3]);
                uint2 u;
                u.x = *(unsigned int*)&p0;
                u.y = *(unsigned int*)&p1;
                *(uint2*)&Ch[(size_t)gr * KOUT + col0 + tx * 4] = u;
            } else {
                float* C = (float*)Cv;
                float4 v = make_float4(f[i][0], f[i][1], f[i][2], f[i][3]);
                *(float4*)&C[(size_t)gr * KOUT + col0 + tx * 4] = v;
            }
        }
    }

    if (L1HEADS) {
        int h = blockIdx.x * 4 + (tx >> 2);
        int cbase = (tx & 3) * 4;
        float wva[4], wvd[4];
#pragma unroll
        for (int j = 0; j < 4; j++) {
            wva[j] = avs[h * HID + cbase + j];
            wvd[j] = avd[h * HID + cbase + j];
        }
#pragma unroll
        for (int i = 0; i < 8; i++) {
            float ps = 0.f, pd = 0.f;
#pragma unroll
            for (int j = 0; j < 4; j++) { ps += f[i][j] * wva[j]; pd += f[i][j] * wvd[j]; }
            ps += __shfl_xor_sync(0xffffffffu, ps, 1);
            pd += __shfl_xor_sync(0xffffffffu, pd, 1);
            ps += __shfl_xor_sync(0xffffffffu, ps, 2);
            pd += __shfl_xor_sync(0xffffffffu, pd, 2);
            int gr = row0 + ty * 8 + i;
            if ((tx & 3) == 0 && gr < M) {
                as_out[(size_t)gr * HEADS + h] = ps;
                ad_out[(size_t)gr * HEADS + h] = pd;
            }
        }
    } else {
        float wva[4], wvd[4];
#pragma unroll
        for (int j = 0; j < 4; j++) {
            wva[j] = avs[tx * 4 + j];
            wvd[j] = avd[tx * 4 + j];
        }
#pragma unroll
        for (int i = 0; i < 8; i++) {
            float ps = 0.f, pd = 0.f;
#pragma unroll
            for (int j = 0; j < 4; j++) { ps += f[i][j] * wva[j]; pd += f[i][j] * wvd[j]; }
#pragma unroll
            for (int d = 1; d <= 8; d <<= 1) {
                ps += __shfl_xor_sync(0xffffffffu, ps, d);
                pd += __shfl_xor_sync(0xffffffffu, pd, d);
            }
            int gr = row0 + ty * 8 + i;
            if (tx == 0 && gr < M) {
                as_out[gr] = ps;
                ad_out[gr] = pd;
            }
        }
    }
}

// ---------------- layer-1 aggregation (warp/dst, half features) ----------------
__global__ void agg1_kernel(const float* __restrict__ b1) {
    int w = (blockIdx.x * blockDim.x + threadIdx.x) >> 5;
    int lane = threadIdx.x & 31;
    if (w >= NN) return;
    int dst = w;
    int beg = g_off[dst], end = g_off[dst + 1];
    int h = lane & 15;
    float adh = g_ad1[(size_t)dst * HEADS + h];
    float exs = __expf(lrelu(g_as1[(size_t)dst * HEADS + h] + adh));
    float denom = exs;
    int srcl = lane >> 1;
    float exm = __shfl_sync(0xffffffffu, exs, srcl);

    float acc[8];
    {
        float4 raw = *(const float4*)&g_h1h[(size_t)dst * F2 + lane * 8];
        const __half2* hp = (const __half2*)&raw;
#pragma unroll
        for (int j = 0; j < 4; j++) {
            float2 v = __half22float2(hp[j]);
            acc[j * 2 + 0] = v.x * exm;
            acc[j * 2 + 1] = v.y * exm;
        }
    }

    for (int i = beg; i < end; i++) {
        int s = g_esrc[i];
        float ex = __expf(lrelu(g_as1[(size_t)s * HEADS + h] + adh));
        denom += ex;
        float em = __shfl_sync(0xffffffffu, ex, srcl);
        float4 raw = *(const float4*)&g_h1h[(size_t)s * F2 + lane * 8];
        const __half2* hp = (const __half2*)&raw;
#pragma unroll
        for (int j = 0; j < 4; j++) {
            float2 v = __half22float2(hp[j]);
            acc[j * 2 + 0] += v.x * em;
            acc[j * 2 + 1] += v.y * em;
        }
    }
    float den = __shfl_sync(0xffffffffu, denom, srcl) + EPSV;
    float inv = 1.0f / den;
    int ch0 = lane * 8;
    float4 o0 = make_float4(acc[0] * inv + b1[ch0 + 0], acc[1] * inv + b1[ch0 + 1],
                            acc[2] * inv + b1[ch0 + 2], acc[3] * inv + b1[ch0 + 3]);
    float4 o1 = make_float4(acc[4] * inv + b1[ch0 + 4], acc[5] * inv + b1[ch0 + 5],
                            acc[6] * inv + b1[ch0 + 6], acc[7] * inv + b1[ch0 + 7]);
    float4* op = (float4*)(g_out1 + (size_t)dst * F2 + ch0);
    op[0] = o0; op[1] = o1;
}

// ---------------- layer-2 aggregation + sigmoid (half features) ----------------
__global__ void agg2_kernel(const float* __restrict__ b2, float* __restrict__ out) {
    int w = (blockIdx.x * blockDim.x + threadIdx.x) >> 5;
    int lane = threadIdx.x & 31;
    if (w >= NN) return;
    int dst = w;
    int beg = g_off[dst], end = g_off[dst + 1];
    float adw = g_ad2[dst];
    float exs = __expf(lrelu(g_as2[dst] + adw));
    float denom = exs;
    float2 v0 = __half22float2(*(const __half2*)&g_h2h[(size_t)dst * OUTC + lane * 2]);
    float2 acc = make_float2(v0.x * exs, v0.y * exs);
    for (int i = beg; i < end; i++) {
        int s = g_esrc[i];
        float ex = __expf(lrelu(g_as2[s] + adw));
        denom += ex;
        float2 sv = __half22float2(*(const __half2*)&g_h2h[(size_t)s * OUTC + lane * 2]);
        acc.x += sv.x * ex; acc.y += sv.y * ex;
    }
    float inv = 1.0f / (denom + EPSV);
    float x0 = acc.x * inv + b2[lane * 2 + 0];
    float x1 = acc.y * inv + b2[lane * 2 + 1];
    float2 o = make_float2(1.0f / (1.0f + __expf(-x0)), 1.0f / (1.0f + __expf(-x1)));
    *(float2*)(out + (size_t)dst * OUTC + lane * 2) = o;
}

// ---------------- launcher -------------------------------------------------------
extern "C" void kernel_launch(void* const* d_in, const int* in_sizes, int n_in,
                              void* d_out, int out_size) {
    const float* x      = (const float*)d_in[0];
    const void*  ei     = d_in[1];
    const float* W1     = (const float*)d_in[2];
    const float* a_src1 = (const float*)d_in[3];
    const float* a_dst1 = (const float*)d_in[4];
    const float* b1     = (const float*)d_in[5];
    const float* W2     = (const float*)d_in[6];
    const float* a_src2 = (const float*)d_in[7];
    const float* a_dst2 = (const float*)d_in[8];
    const float* b2     = (const float*)d_in[9];
    float* out = (float*)d_out;

    void *h1, *h2;
    float *o1, *as1, *ad1, *as2, *ad2;
    cudaGetSymbolAddress(&h1, g_h1h);
    cudaGetSymbolAddress((void**)&o1, g_out1);
    cudaGetSymbolAddress(&h2, g_h2h);
    cudaGetSymbolAddress((void**)&as1, g_as1);
    cudaGetSymbolAddress((void**)&ad1, g_ad1);
    cudaGetSymbolAddress((void**)&as2, g_as2);
    cudaGetSymbolAddress((void**)&ad2, g_ad2);

    // one-time side stream + events (created on the uncaptured correctness call)
    static cudaStream_t s_side = 0;
    static cudaEvent_t evF = 0, evJ = 0;
    if (!s_side) {
        cudaStreamCreateWithFlags(&s_side, cudaStreamNonBlocking);
        cudaEventCreateWithFlags(&evF, cudaEventDisableTiming);
        cudaEventCreateWithFlags(&evJ, cudaEventDisableTiming);
    }

    // fork: CSR build on side stream, GEMM1 on main stream
    cudaEventRecord(evF, 0);
    cudaStreamWaitEvent(s_side, evF, 0);

    init_kernel<<<(NN + 255) / 256, 256, 0, s_side>>>(ei);
    hist_kernel<<<(EE + 255) / 256, 256, 0, s_side>>>(ei);
    scanA_kernel<<<SCAN_BLK, 1024, 0, s_side>>>();
    scanB_kernel<<<1, 64, 0, s_side>>>();
    scanC_kernel<<<SCAN_BLK, 1024, 0, s_side>>>();
    scatter_kernel<<<(EE + 255) / 256, 256, 0, s_side>>>(ei);
    cudaEventRecord(evJ, s_side);

    {
        dim3 grid(F2 / 64, (NN + 127) / 128);
        gemm_fused<F1, F2, true, true><<<grid, 256>>>(x, W1, h1, a_src1, a_dst1, as1, ad1, NN);
    }

    // join
    cudaStreamWaitEvent(0, evJ, 0);

    agg1_kernel<<<(NN * 32 + 255) / 256, 256>>>(b1);

    {
        dim3 grid(OUTC / 64, (NN + 127) / 128);
        gemm_fused<F2, OUTC, false, true><<<grid, 256>>>(o1, W2, h2, a_src2, a_dst2, as2, ad2, NN);
    }
    agg2_kernel<<<(NN * 32 + 255) / 256, 256>>>(b2, out);
}

// round 4
// speedup vs baseline: 2.2192x; 1.3929x over previous
#include <cuda_runtime.h>
#include <cuda_fp16.h>
#include <cuda_bf16.h>

#define NN 50000
#define EE 800000
#define F1 128
#define F2 256   // HEADS*HID
#define HEADS 16
#define HID 16
#define OUTC 64
#define NEG_SLOPE 0.2f
#define EPSV 1e-16f
#define SCAN_BLK 49

// ---------------- scratch ----------------------------------------------------
__device__ __half g_xh[(size_t)NN * F1];     // x in half
__device__ __half g_w1h[F1 * F2];
__device__ __half g_w2h[F2 * OUTC];
__device__ __half g_h1h[(size_t)NN * F2];    // layer-1 features (half)
__device__ __half g_out1h[(size_t)NN * F2];  // layer-1 output (half)
__device__ __half g_h2h[(size_t)NN * OUTC];  // layer-2 features (half)
__device__ float  g_as1[(size_t)NN * HEADS];
__device__ float  g_ad1[(size_t)NN * HEADS];
__device__ float  g_as2[NN];
__device__ float  g_ad2[NN];
__device__ int    g_cnt[NN];
__device__ int    g_cur[NN];
__device__ int    g_off[NN + 1];
__device__ int    g_esrc[EE];
__device__ int    g_bsum[64];
__device__ int    g_bpre[64];
__device__ int    g_eflag;

// ---------------- helpers -----------------------------------------------------
__device__ __forceinline__ float lrelu(float e) { return e > 0.f ? e : NEG_SLOPE * e; }

__device__ __forceinline__ void load_edge(const void* ei, int i, int flag, int& s, int& d) {
    if (flag) {
        const int* p = (const int*)ei;
        s = p[i]; d = p[EE + i];
    } else {
        const long long* p = (const long long*)ei;
        s = (int)p[i]; d = (int)p[EE + i];
    }
}

__device__ __forceinline__ void hmma16816(float* d, const unsigned* a, const unsigned* b) {
    asm volatile(
        "mma.sync.aligned.m16n8k16.row.col.f32.f16.f16.f32 "
        "{%0,%1,%2,%3}, {%4,%5,%6,%7}, {%8,%9}, {%0,%1,%2,%3};"
        : "+f"(d[0]), "+f"(d[1]), "+f"(d[2]), "+f"(d[3])
        : "r"(a[0]), "r"(a[1]), "r"(a[2]), "r"(a[3]), "r"(b[0]), "r"(b[1]));
}

// ---------------- float -> half convert ----------------------------------------
__global__ void f2h_kernel(const float* __restrict__ in, __half* __restrict__ out, int n4) {
    int i = blockIdx.x * blockDim.x + threadIdx.x;
    if (i >= n4) return;
    float4 v = ((const float4*)in)[i];
    __half2 p0 = __floats2half2_rn(v.x, v.y);
    __half2 p1 = __floats2half2_rn(v.z, v.w);
    uint2 u;
    u.x = *(unsigned*)&p0;
    u.y = *(unsigned*)&p1;
    ((uint2*)out)[i] = u;
}

// ---------------- init + CSR build ----------------------------------------------
__global__ void init_kernel(const void* ei) {
    int i = blockIdx.x * blockDim.x + threadIdx.x;
    if (i < NN) { g_cnt[i] = 0; g_cur[i] = 0; }
    if (blockIdx.x == 0) {
        __shared__ int nz;
        if (threadIdx.x == 0) nz = 0;
        __syncthreads();
        const int* w = (const int*)ei;
        int any = 0;
        for (int j = threadIdx.x; j < 512; j += blockDim.x)
            if (w[2 * j + 1] != 0) any = 1;
        if (any) atomicOr(&nz, 1);
        __syncthreads();
        if (threadIdx.x == 0) g_eflag = nz ? 1 : 0;
    }
}

__global__ void hist_kernel(const void* ei) {
    int i = blockIdx.x * blockDim.x + threadIdx.x;
    if (i >= EE) return;
    int s, d;
    load_edge(ei, i, g_eflag, s, d);
    atomicAdd(&g_cnt[d], 1);
}

__global__ void scanA_kernel() {
    __shared__ int wsum[32];
    int i = blockIdx.x * 1024 + threadIdx.x;
    int lane = threadIdx.x & 31, wid = threadIdx.x >> 5;
    int x = (i < NN) ? g_cnt[i] : 0;
    int incl = x;
#pragma unroll
    for (int d = 1; d < 32; d <<= 1) {
        int t = __shfl_up_sync(0xffffffffu, incl, d);
        if (lane >= d) incl += t;
    }
    if (lane == 31) wsum[wid] = incl;
    __syncthreads();
    if (wid == 0) {
        int y = wsum[lane];
#pragma unroll
        for (int d = 1; d < 32; d <<= 1) {
            int t = __shfl_up_sync(0xffffffffu, y, d);
            if (lane >= d) y += t;
        }
        wsum[lane] = y;
    }
    __syncthreads();
    if (wid > 0) incl += wsum[wid - 1];
    if (i < NN) g_off[i + 1] = incl;
    if (threadIdx.x == 1023) g_bsum[blockIdx.x] = incl;
}

__global__ void scanB_kernel() {
    __shared__ int s[64];
    int t = threadIdx.x;
    int v0 = (t < SCAN_BLK) ? g_bsum[t] : 0;
    s[t] = v0;
    __syncthreads();
#pragma unroll
    for (int d = 1; d < 64; d <<= 1) {
        int v = (t >= d) ? s[t - d] : 0;
        __syncthreads();
        s[t] += v;
        __syncthreads();
    }
    g_bpre[t] = s[t] - v0;
}

__global__ void scanC_kernel() {
    int i = blockIdx.x * 1024 + threadIdx.x;
    if (i < NN) g_off[i + 1] += g_bpre[blockIdx.x];
    if (i == 0) g_off[0] = 0;
}

__global__ void scatter_kernel(const void* ei) {
    int i = blockIdx.x * blockDim.x + threadIdx.x;
    if (i >= EE) return;
    int s, d;
    load_edge(ei, i, g_eflag, s, d);
    int pos = g_off[d] + atomicAdd(&g_cur[d], 1);
    g_esrc[pos] = s;
}

// ---------------- HMMA GEMM + fused alpha dots ----------------------------------
// C[M,KOUT] = A[M,KIN] @ B[KIN,KOUT], all half (fp32 accum).
// Block tile 128x64, 8 warps: wm = wid%4 (32 rows), wn = wid/4 (32 cols).
// KCH=64 smem stage. B staged transposed: Bst[n][k].
template <int KIN, int KOUT, bool L1HEADS>
__global__ void gemm_hmma(const __half* __restrict__ A, const __half* __restrict__ B,
                          __half* __restrict__ C,
                          const float* __restrict__ avs, const float* __restrict__ avd,
                          float* __restrict__ as_out, float* __restrict__ ad_out,
                          int M) {
    __shared__ __half As[128][72];
    __shared__ __half Bst[64][72];
    __shared__ float sAs[128], sAd[128];

    int tid = threadIdx.x;                 // 256
    int wid = tid >> 5, lane = tid & 31;
    int wm = wid & 3, wn = wid >> 2;
    int row0 = blockIdx.y * 128, col0 = blockIdx.x * 64;
    int lr = lane >> 2;                    // 0..7
    int lc = lane & 3;                     // 0..3

    float d[2][4][4];
#pragma unroll
    for (int a = 0; a < 2; a++)
#pragma unroll
        for (int b = 0; b < 4; b++)
#pragma unroll
            for (int c = 0; c < 4; c++) d[a][b][c] = 0.f;

    for (int k0 = 0; k0 < KIN; k0 += 64) {
        // load A tile [128 x 64]
#pragma unroll
        for (int l = 0; l < 4; l++) {
            int idx = tid + l * 256;          // 0..1023 = 128 rows x 8 chunks
            int r = idx >> 3, c8 = idx & 7;
            int gr = row0 + r;
            float4 v = make_float4(0.f, 0.f, 0.f, 0.f);
            if (gr < M) v = *(const float4*)&A[(size_t)gr * KIN + k0 + c8 * 8];
            *(float4*)&As[r][c8 * 8] = v;
        }
        // load B tile transposed: Bst[n][k]
#pragma unroll
        for (int l = 0; l < 2; l++) {
            int idx = tid + l * 256;          // 0..511 = 64 k-rows x 8 n-chunks
            int kr = idx >> 3, n8 = idx & 7;
            float4 v = *(const float4*)&B[(size_t)(k0 + kr) * KOUT + col0 + n8 * 8];
            const __half* hv = (const __half*)&v;
#pragma unroll
            for (int j = 0; j < 8; j++) Bst[n8 * 8 + j][kr] = hv[j];
        }
        __syncthreads();

#pragma unroll
        for (int kk = 0; kk < 4; kk++) {
            int kb = kk * 16;
            unsigned afr[2][4], bfr[4][2];
#pragma unroll
            for (int mt = 0; mt < 2; mt++) {
                int r = wm * 32 + mt * 16 + lr;
                afr[mt][0] = *(const unsigned*)&As[r][kb + lc * 2];
                afr[mt][1] = *(const unsigned*)&As[r + 8][kb + lc * 2];
                afr[mt][2] = *(const unsigned*)&As[r][kb + lc * 2 + 8];
                afr[mt][3] = *(const unsigned*)&As[r + 8][kb + lc * 2 + 8];
            }
#pragma unroll
            for (int nt = 0; nt < 4; nt++) {
                int n = wn * 32 + nt * 8 + lr;
                bfr[nt][0] = *(const unsigned*)&Bst[n][kb + lc * 2];
                bfr[nt][1] = *(const unsigned*)&Bst[n][kb + lc * 2 + 8];
            }
#pragma unroll
            for (int mt = 0; mt < 2; mt++)
#pragma unroll
                for (int nt = 0; nt < 4; nt++)
                    hmma16816(d[mt][nt], afr[mt], bfr[nt]);
        }
        __syncthreads();
    }

    // store C (half)
#pragma unroll
    for (int mt = 0; mt < 2; mt++) {
        int gr0 = row0 + wm * 32 + mt * 16 + lr;
#pragma unroll
        for (int nt = 0; nt < 4; nt++) {
            int gc = col0 + wn * 32 + nt * 8 + lc * 2;
            if (gr0 < M) {
                __half2 p = __floats2half2_rn(d[mt][nt][0], d[mt][nt][1]);
                *(unsigned*)&C[(size_t)gr0 * KOUT + gc] = *(unsigned*)&p;
            }
            if (gr0 + 8 < M) {
                __half2 p = __floats2half2_rn(d[mt][nt][2], d[mt][nt][3]);
                *(unsigned*)&C[(size_t)(gr0 + 8) * KOUT + gc] = *(unsigned*)&p;
            }
        }
    }

    // fused alpha dots (fp32 fragments)
    if (L1HEADS) {
        // two heads per warp: head hp uses nt = 2*hp, 2*hp+1
#pragma unroll
        for (int mt = 0; mt < 2; mt++) {
#pragma unroll
            for (int hp = 0; hp < 2; hp++) {
                int h = blockIdx.x * 4 + wn * 2 + hp;
                float psr = 0.f, pdr = 0.f, psr8 = 0.f, pdr8 = 0.f;
#pragma unroll
                for (int half_t = 0; half_t < 2; half_t++) {
                    int nt = hp * 2 + half_t;
                    int cl = half_t * 8 + lc * 2;
                    float w0s = avs[h * HID + cl], w1s = avs[h * HID + cl + 1];
                    float w0d = avd[h * HID + cl], w1d = avd[h * HID + cl + 1];
                    psr  += d[mt][nt][0] * w0s + d[mt][nt][1] * w1s;
                    pdr  += d[mt][nt][0] * w0d + d[mt][nt][1] * w1d;
                    psr8 += d[mt][nt][2] * w0s + d[mt][nt][3] * w1s;
                    pdr8 += d[mt][nt][2] * w0d + d[mt][nt][3] * w1d;
                }
#pragma unroll
                for (int dx = 1; dx <= 2; dx <<= 1) {
                    psr  += __shfl_xor_sync(0xffffffffu, psr, dx);
                    pdr  += __shfl_xor_sync(0xffffffffu, pdr, dx);
                    psr8 += __shfl_xor_sync(0xffffffffu, psr8, dx);
                    pdr8 += __shfl_xor_sync(0xffffffffu, pdr8, dx);
                }
                if (lc == 0) {
                    int gr = row0 + wm * 32 + mt * 16 + lr;
                    if (gr < M) {
                        as_out[(size_t)gr * HEADS + h] = psr;
                        ad_out[(size_t)gr * HEADS + h] = pdr;
                    }
                    if (gr + 8 < M) {
                        as_out[(size_t)(gr + 8) * HEADS + h] = psr8;
                        ad_out[(size_t)(gr + 8) * HEADS + h] = pdr8;
                    }
                }
            }
        }
    } else {
        // single head over 64 cols: cross-warp (wn) reduction via smem
#pragma unroll
        for (int mt = 0; mt < 2; mt++) {
            float psr = 0.f, pdr = 0.f, psr8 = 0.f, pdr8 = 0.f;
#pragma unroll
            for (int nt = 0; nt < 4; nt++) {
                int cl = wn * 32 + nt * 8 + lc * 2;
                float w0s = avs[cl], w1s = avs[cl + 1];
                float w0d = avd[cl], w1d = avd[cl + 1];
                psr  += d[mt][nt][0] * w0s + d[mt][nt][1] * w1s;
                pdr  += d[mt][nt][0] * w0d + d[mt][nt][1] * w1d;
                psr8 += d[mt][nt][2] * w0s + d[mt][nt][3] * w1s;
                pdr8 += d[mt][nt][2] * w0d + d[mt][nt][3] * w1d;
            }
#pragma unroll
            for (int dx = 1; dx <= 2; dx <<= 1) {
                psr  += __shfl_xor_sync(0xffffffffu, psr, dx);
                pdr  += __shfl_xor_sync(0xffffffffu, pdr, dx);
                psr8 += __shfl_xor_sync(0xffffffffu, psr8, dx);
                pdr8 += __shfl_xor_sync(0xffffffffu, pdr8, dx);
            }
            if (lc == 0 && wn == 0) {
                int lrow = wm * 32 + mt * 16 + lr;
                sAs[lrow] = psr;  sAd[lrow] = pdr;
                sAs[lrow + 8] = psr8; sAd[lrow + 8] = pdr8;
            }
            __syncthreads();
            if (lc == 0 && wn == 1) {
                int lrow = wm * 32 + mt * 16 + lr;
                int gr = row0 + lrow;
                if (gr < M) {
                    as_out[gr] = sAs[lrow] + psr;
                    ad_out[gr] = sAd[lrow] + pdr;
                }
                if (gr + 8 < M) {
                    as_out[gr + 8] = sAs[lrow + 8] + psr8;
                    ad_out[gr + 8] = sAd[lrow + 8] + pdr8;
                }
            }
            __syncthreads();
        }
    }
}

// ---------------- layer-1 aggregation (warp/dst, half in, half out) ------------
__global__ void agg1_kernel(const float* __restrict__ b1) {
    int w = (blockIdx.x * blockDim.x + threadIdx.x) >> 5;
    int lane = threadIdx.x & 31;
    if (w >= NN) return;
    int dst = w;
    int beg = g_off[dst], end = g_off[dst + 1];
    int h = lane & 15;
    float adh = g_ad1[(size_t)dst * HEADS + h];
    float exs = __expf(lrelu(g_as1[(size_t)dst * HEADS + h] + adh));
    float denom = exs;
    int srcl = lane >> 1;
    float exm = __shfl_sync(0xffffffffu, exs, srcl);

    float acc[8];
    {
        float4 raw = *(const float4*)&g_h1h[(size_t)dst * F2 + lane * 8];
        const __half2* hp = (const __half2*)&raw;
#pragma unroll
        for (int j = 0; j < 4; j++) {
            float2 v = __half22float2(hp[j]);
            acc[j * 2 + 0] = v.x * exm;
            acc[j * 2 + 1] = v.y * exm;
        }
    }
    for (int i = beg; i < end; i++) {
        int s = g_esrc[i];
        float ex = __expf(lrelu(g_as1[(size_t)s * HEADS + h] + adh));
        denom += ex;
        float em = __shfl_sync(0xffffffffu, ex, srcl);
        float4 raw = *(const float4*)&g_h1h[(size_t)s * F2 + lane * 8];
        const __half2* hp = (const __half2*)&raw;
#pragma unroll
        for (int j = 0; j < 4; j++) {
            float2 v = __half22float2(hp[j]);
            acc[j * 2 + 0] += v.x * em;
            acc[j * 2 + 1] += v.y * em;
        }
    }
    float den = __shfl_sync(0xffffffffu, denom, srcl) + EPSV;
    float inv = 1.0f / den;
    int ch0 = lane * 8;
    __half2 o[4];
#pragma unroll
    for (int j = 0; j < 4; j++)
        o[j] = __floats2half2_rn(acc[j * 2 + 0] * inv + b1[ch0 + j * 2 + 0],
                                 acc[j * 2 + 1] * inv + b1[ch0 + j * 2 + 1]);
    *(uint2*)&g_out1h[(size_t)dst * F2 + ch0] = *(uint2*)&o[0];
    *(uint2*)&g_out1h[(size_t)dst * F2 + ch0 + 4] = *(uint2*)&o[2];
}

// ---------------- layer-2 aggregation + sigmoid ---------------------------------
__global__ void agg2_kernel(const float* __restrict__ b2, float* __restrict__ out) {
    int w = (blockIdx.x * blockDim.x + threadIdx.x) >> 5;
    int lane = threadIdx.x & 31;
    if (w >= NN) return;
    int dst = w;
    int beg = g_off[dst], end = g_off[dst + 1];
    float adw = g_ad2[dst];
    float exs = __expf(lrelu(g_as2[dst] + adw));
    float denom = exs;
    float2 v0 = __half22float2(*(const __half2*)&g_h2h[(size_t)dst * OUTC + lane * 2]);
    float2 acc = make_float2(v0.x * exs, v0.y * exs);
    for (int i = beg; i < end; i++) {
        int s = g_esrc[i];
        float ex = __expf(lrelu(g_as2[s] + adw));
        denom += ex;
        float2 sv = __half22float2(*(const __half2*)&g_h2h[(size_t)s * OUTC + lane * 2]);
        acc.x += sv.x * ex; acc.y += sv.y * ex;
    }
    float inv = 1.0f / (denom + EPSV);
    float x0 = acc.x * inv + b2[lane * 2 + 0];
    float x1 = acc.y * inv + b2[lane * 2 + 1];
    float2 o = make_float2(1.0f / (1.0f + __expf(-x0)), 1.0f / (1.0f + __expf(-x1)));
    *(float2*)(out + (size_t)dst * OUTC + lane * 2) = o;
}

// ---------------- launcher -------------------------------------------------------
extern "C" void kernel_launch(void* const* d_in, const int* in_sizes, int n_in,
                              void* d_out, int out_size) {
    const float* x      = (const float*)d_in[0];
    const void*  ei     = d_in[1];
    const float* W1     = (const float*)d_in[2];
    const float* a_src1 = (const float*)d_in[3];
    const float* a_dst1 = (const float*)d_in[4];
    const float* b1     = (const float*)d_in[5];
    const float* W2     = (const float*)d_in[6];
    const float* a_src2 = (const float*)d_in[7];
    const float* a_dst2 = (const float*)d_in[8];
    const float* b2     = (const float*)d_in[9];
    float* out = (float*)d_out;

    __half *xh, *w1h, *w2h, *h1, *o1, *h2;
    float *as1, *ad1, *as2, *ad2;
    cudaGetSymbolAddress((void**)&xh, g_xh);
    cudaGetSymbolAddress((void**)&w1h, g_w1h);
    cudaGetSymbolAddress((void**)&w2h, g_w2h);
    cudaGetSymbolAddress((void**)&h1, g_h1h);
    cudaGetSymbolAddress((void**)&o1, g_out1h);
    cudaGetSymbolAddress((void**)&h2, g_h2h);
    cudaGetSymbolAddress((void**)&as1, g_as1);
    cudaGetSymbolAddress((void**)&ad1, g_ad1);
    cudaGetSymbolAddress((void**)&as2, g_as2);
    cudaGetSymbolAddress((void**)&ad2, g_ad2);

    static cudaStream_t s_side = 0;
    static cudaEvent_t evF = 0, evJ = 0;
    if (!s_side) {
        cudaStreamCreateWithFlags(&s_side, cudaStreamNonBlocking);
        cudaEventCreateWithFlags(&evF, cudaEventDisableTiming);
        cudaEventCreateWithFlags(&evJ, cudaEventDisableTiming);
    }

    // fork: CSR build on side stream
    cudaEventRecord(evF, 0);
    cudaStreamWaitEvent(s_side, evF, 0);
    init_kernel<<<(NN + 255) / 256, 256, 0, s_side>>>(ei);
    hist_kernel<<<(EE + 255) / 256, 256, 0, s_side>>>(ei);
    scanA_kernel<<<SCAN_BLK, 1024, 0, s_side>>>();
    scanB_kernel<<<1, 64, 0, s_side>>>();
    scanC_kernel<<<SCAN_BLK, 1024, 0, s_side>>>();
    scatter_kernel<<<(EE + 255) / 256, 256, 0, s_side>>>(ei);
    cudaEventRecord(evJ, s_side);

    // main stream: converts + GEMM1
    f2h_kernel<<<(NN * F1 / 4 + 255) / 256, 256>>>(x, xh, NN * F1 / 4);
    f2h_kernel<<<(F1 * F2 / 4 + 255) / 256, 256>>>(W1, w1h, F1 * F2 / 4);
    f2h_kernel<<<(F2 * OUTC / 4 + 255) / 256, 256>>>(W2, w2h, F2 * OUTC / 4);
    {
        dim3 grid(F2 / 64, (NN + 127) / 128);
        gemm_hmma<F1, F2, true><<<grid, 256>>>(xh, w1h, h1, a_src1, a_dst1, as1, ad1, NN);
    }

    cudaStreamWaitEvent(0, evJ, 0);

    agg1_kernel<<<(NN * 32 + 255) / 256, 256>>>(b1);
    {
        dim3 grid(OUTC / 64, (NN + 127) / 128);
        gemm_hmma<F2, OUTC, false><<<grid, 256>>>(o1, w2h, h2, a_src2, a_dst2, as2, ad2, NN);
    }
    agg2_kernel<<<(NN * 32 + 255) / 256, 256>>>(b2, out);
}